// round 2
// baseline (speedup 1.0000x reference)
#include <cuda_runtime.h>
#include <cstdint>

// ---------------------------------------------------------------------------
// UncertainTemporalAttention: N=8192 tokens, D=256.
//   q = 0.125*(x Wq^T + bq); k = x Wk^T + bk; v = x Wv^T + bv; vv = xv Wvar^T + bvar
//   P = exp(q k^T)  (raw exp is safe: logits ~ +-5)
//   rowsum_i = sum_j P_ij
//   out_mean = ((P v)/rowsum) Wo^T + bo
//   out_var  = (P.^2 vv) / rowsum^2
// All GEMMs are "NT" (C = A * B^T, both K-contiguous). Split-tf32 (3-term
// Markidis) mma.sync m16n8k8 for ~fp32 accuracy.
// ---------------------------------------------------------------------------

#define DEV_INLINE __device__ __forceinline__

constexpr int N_TOK = 8192;
constexpr int DIM   = 256;

__device__ float g_q  [N_TOK * DIM];
__device__ float g_k  [N_TOK * DIM];
__device__ float g_vT [DIM * N_TOK];
__device__ float g_vvT[DIM * N_TOK];
__device__ float g_tmp[N_TOK * DIM];
__device__ float g_rs [N_TOK];
__device__ float g_P  [(size_t)N_TOK * N_TOK];   // 256 MB

enum { EPI_BIAS = 0, EPI_EXP = 1, EPI_DIV = 2, EPI_DIV2 = 3 };

DEV_INLINE uint32_t smem_u32(const void* p) {
    return (uint32_t)__cvta_generic_to_shared(p);
}

DEV_INLINE void ldsm4(uint32_t* r, uint32_t a) {
    asm volatile("ldmatrix.sync.aligned.m8n8.x4.shared.b16 {%0,%1,%2,%3}, [%4];"
                 : "=r"(r[0]), "=r"(r[1]), "=r"(r[2]), "=r"(r[3]) : "r"(a));
}

DEV_INLINE void mma_tf32(float* c, const uint32_t* a, uint32_t b0, uint32_t b1) {
    asm volatile(
        "mma.sync.aligned.m16n8k8.row.col.f32.tf32.tf32.f32 "
        "{%0,%1,%2,%3},{%4,%5,%6,%7},{%8,%9},{%0,%1,%2,%3};"
        : "+f"(c[0]), "+f"(c[1]), "+f"(c[2]), "+f"(c[3])
        : "r"(a[0]), "r"(a[1]), "r"(a[2]), "r"(a[3]), "r"(b0), "r"(b1));
}

DEV_INLINE void cp16(uint32_t s, const void* g) {
    asm volatile("cp.async.cg.shared.global [%0], [%1], 16;" :: "r"(s), "l"(g));
}

// split x into tf32 hi + tf32 lo (Markidis)
DEV_INLINE void tf32_split(float x, uint32_t& hi, uint32_t& lo) {
    asm("cvt.rna.tf32.f32 %0, %1;" : "=r"(hi) : "f"(x));
    float r = x - __uint_as_float(hi);
    asm("cvt.rna.tf32.f32 %0, %1;" : "=r"(lo) : "f"(r));
}

// C[M,N] = epilogue( A[M,K] * B[N,K]^T )
// CTA 128x128, K-chunk 32, 256 threads (2x4 warps), warp tile 64x32.
template <int EPI, bool SQA, bool TRANS>
__global__ void __launch_bounds__(256)
gemm_nt(const float* __restrict__ A, const float* __restrict__ B,
        float* __restrict__ C, int M, int N, int K,
        const float* __restrict__ bias, const float* __restrict__ rowsum,
        float outScale)
{
    extern __shared__ char smem_raw[];
    const uint32_t s_base = smem_u32(smem_raw);

    const int tid  = threadIdx.x;
    const int warp = tid >> 5, lane = tid & 31;
    const int wm = warp >> 2, wn = warp & 3;
    const int bm = blockIdx.y, bn = blockIdx.x;

    const float* Ab = A + (size_t)bm * 128 * K;
    const float* Bb = B + (size_t)bn * 128 * K;

    float c[4][4][4];
#pragma unroll
    for (int i = 0; i < 4; i++)
#pragma unroll
        for (int j = 0; j < 4; j++)
#pragma unroll
            for (int l = 0; l < 4; l++) c[i][j][l] = 0.f;

    auto issue = [&](int stage, int kc) {
        const uint32_t sA = s_base + (uint32_t)stage * 32768u;
        const uint32_t sB = sA + 16384u;
        const int k0 = kc * 32;
#pragma unroll
        for (int i = 0; i < 4; i++) {
            int v = tid + i * 256;
            int row = v >> 3, ch = v & 7;
            uint32_t off = (uint32_t)(row * 128 + ((ch ^ (row & 7)) << 4));
            cp16(sA + off, Ab + (size_t)row * K + k0 + ch * 4);
            cp16(sB + off, Bb + (size_t)row * K + k0 + ch * 4);
        }
        asm volatile("cp.async.commit_group;");
    };

    auto compute = [&](int stage) {
        const uint32_t sA = s_base + (uint32_t)stage * 32768u;
        const uint32_t sB = sA + 16384u;
        const int lg = lane >> 3, li = lane & 7;
#pragma unroll
        for (int s8 = 0; s8 < 4; s8++) {
            uint32_t ah[4][4], al[4][4];
#pragma unroll
            for (int mt = 0; mt < 4; mt++) {
                uint32_t a[4];
                int row = wm * 64 + mt * 16 + (lg & 1) * 8 + li;
                int ch  = s8 * 2 + (lg >> 1);
                ldsm4(a, sA + row * 128 + ((ch ^ (row & 7)) << 4));
#pragma unroll
                for (int q = 0; q < 4; q++) {
                    float f = __uint_as_float(a[q]);
                    if (SQA) f *= f;
                    tf32_split(f, ah[mt][q], al[mt][q]);
                }
            }
            uint32_t bh[2][4], bl[2][4];
#pragma unroll
            for (int p = 0; p < 2; p++) {
                uint32_t b[4];
                int row = wn * 32 + p * 16 + (lg >> 1) * 8 + li;
                int ch  = s8 * 2 + (lg & 1);
                ldsm4(b, sB + row * 128 + ((ch ^ (row & 7)) << 4));
#pragma unroll
                for (int q = 0; q < 4; q++)
                    tf32_split(__uint_as_float(b[q]), bh[p][q], bl[p][q]);
            }
#pragma unroll
            for (int mt = 0; mt < 4; mt++)
#pragma unroll
                for (int nt = 0; nt < 4; nt++) {
                    const int p = nt >> 1, o = (nt & 1) * 2;
                    mma_tf32(c[mt][nt], ah[mt], bh[p][o], bh[p][o + 1]); // hi*hi
                    mma_tf32(c[mt][nt], ah[mt], bl[p][o], bl[p][o + 1]); // hi*lo
                    mma_tf32(c[mt][nt], al[mt], bh[p][o], bh[p][o + 1]); // lo*hi
                }
        }
    };

    const int nk = K >> 5;
    issue(0, 0);
    for (int kc = 0; kc < nk; kc++) {
        if (kc + 1 < nk) {
            issue((kc + 1) & 1, kc + 1);
            asm volatile("cp.async.wait_group 1;");
        } else {
            asm volatile("cp.async.wait_group 0;");
        }
        __syncthreads();
        compute(kc & 1);
        __syncthreads();
    }

    // --- epilogue ---
    const int gr0 = bm * 128 + wm * 64;
    const int gc0 = bn * 128 + wn * 32;
#pragma unroll
    for (int mt = 0; mt < 4; mt++) {
#pragma unroll
        for (int rr = 0; rr < 2; rr++) {
            int row = gr0 + mt * 16 + rr * 8 + (lane >> 2);
            float rfac = 1.f;
            if (EPI == EPI_DIV)  rfac = 1.f / rowsum[row];
            if (EPI == EPI_DIV2) { float s = rowsum[row]; rfac = 1.f / (s * s); }
#pragma unroll
            for (int nt = 0; nt < 4; nt++) {
                int col = gc0 + nt * 8 + (lane & 3) * 2;
                float v0 = c[mt][nt][rr * 2 + 0];
                float v1 = c[mt][nt][rr * 2 + 1];
                if (EPI == EPI_BIAS) {
                    v0 = (v0 + bias[col])     * outScale;
                    v1 = (v1 + bias[col + 1]) * outScale;
                } else if (EPI == EPI_EXP) {
                    v0 = __expf(v0); v1 = __expf(v1);
                } else {
                    v0 *= rfac; v1 *= rfac;
                }
                if (TRANS) {
                    C[(size_t)col * M + row]       = v0;
                    C[(size_t)(col + 1) * M + row] = v1;
                } else {
                    *reinterpret_cast<float2*>(&C[(size_t)row * N + col]) =
                        make_float2(v0, v1);
                }
            }
        }
    }
}

// rowsum over P, one block per row, deterministic (no atomics)
__global__ void rowsum_kernel(const float* __restrict__ P, float* __restrict__ rs)
{
    const int row = blockIdx.x;
    const float4* p = reinterpret_cast<const float4*>(P + (size_t)row * N_TOK);
    float s = 0.f;
    for (int i = threadIdx.x; i < N_TOK / 4; i += 256) {
        float4 v = p[i];
        s += (v.x + v.y) + (v.z + v.w);
    }
#pragma unroll
    for (int o = 16; o > 0; o >>= 1) s += __shfl_xor_sync(0xffffffffu, s, o);
    __shared__ float ws[8];
    if ((threadIdx.x & 31) == 0) ws[threadIdx.x >> 5] = s;
    __syncthreads();
    if (threadIdx.x == 0) {
        float t = 0.f;
#pragma unroll
        for (int w = 0; w < 8; w++) t += ws[w];
        rs[row] = t;
    }
}

extern "C" void kernel_launch(void* const* d_in, const int* in_sizes, int n_in,
                              void* d_out, int out_size)
{
    (void)in_sizes; (void)n_in; (void)out_size;
    const float* x_mean = (const float*)d_in[0];
    const float* x_var  = (const float*)d_in[1];
    // d_in[2]=edge_index (unused), d_in[3]=edge_timestamps (unused)
    const float* Wq = (const float*)d_in[4];  const float* bq = (const float*)d_in[5];
    const float* Wk = (const float*)d_in[6];  const float* bk = (const float*)d_in[7];
    const float* Wv = (const float*)d_in[8];  const float* bv = (const float*)d_in[9];
    const float* Wo = (const float*)d_in[10]; const float* bo = (const float*)d_in[11];
    const float* Wvar = (const float*)d_in[12]; const float* bvar = (const float*)d_in[13];

    float* out_mean = (float*)d_out;
    float* out_var  = out_mean + (size_t)N_TOK * DIM;

    float *q, *k, *vT, *vvT, *tmp, *P, *rs;
    cudaGetSymbolAddress((void**)&q,   g_q);
    cudaGetSymbolAddress((void**)&k,   g_k);
    cudaGetSymbolAddress((void**)&vT,  g_vT);
    cudaGetSymbolAddress((void**)&vvT, g_vvT);
    cudaGetSymbolAddress((void**)&tmp, g_tmp);
    cudaGetSymbolAddress((void**)&P,   g_P);
    cudaGetSymbolAddress((void**)&rs,  g_rs);

    const int SMEM = 65536;
    cudaFuncSetAttribute(gemm_nt<EPI_BIAS, false, false>, cudaFuncAttributeMaxDynamicSharedMemorySize, SMEM);
    cudaFuncSetAttribute(gemm_nt<EPI_BIAS, false, true >, cudaFuncAttributeMaxDynamicSharedMemorySize, SMEM);
    cudaFuncSetAttribute(gemm_nt<EPI_EXP,  false, false>, cudaFuncAttributeMaxDynamicSharedMemorySize, SMEM);
    cudaFuncSetAttribute(gemm_nt<EPI_DIV,  false, false>, cudaFuncAttributeMaxDynamicSharedMemorySize, SMEM);
    cudaFuncSetAttribute(gemm_nt<EPI_DIV2, true,  false>, cudaFuncAttributeMaxDynamicSharedMemorySize, SMEM);

    dim3 blk(256);
    dim3 gProj(DIM / 128, N_TOK / 128);     // (2, 64)
    dim3 gAttn(N_TOK / 128, N_TOK / 128);   // (64, 64)

    gemm_nt<EPI_BIAS, false, false><<<gProj, blk, SMEM>>>(x_mean, Wq,   q,   N_TOK, DIM, DIM, bq,   nullptr, 0.125f);
    gemm_nt<EPI_BIAS, false, false><<<gProj, blk, SMEM>>>(x_mean, Wk,   k,   N_TOK, DIM, DIM, bk,   nullptr, 1.f);
    gemm_nt<EPI_BIAS, false, true ><<<gProj, blk, SMEM>>>(x_mean, Wv,   vT,  N_TOK, DIM, DIM, bv,   nullptr, 1.f);
    gemm_nt<EPI_BIAS, false, true ><<<gProj, blk, SMEM>>>(x_var,  Wvar, vvT, N_TOK, DIM, DIM, bvar, nullptr, 1.f);

    gemm_nt<EPI_EXP, false, false><<<gAttn, blk, SMEM>>>(q, k, P, N_TOK, N_TOK, DIM, nullptr, nullptr, 1.f);

    rowsum_kernel<<<N_TOK, 256>>>(P, rs);

    gemm_nt<EPI_DIV,  false, false><<<gProj, blk, SMEM>>>(P, vT,  tmp,     N_TOK, DIM, N_TOK, nullptr, rs, 1.f);
    gemm_nt<EPI_DIV2, true,  false><<<gProj, blk, SMEM>>>(P, vvT, out_var, N_TOK, DIM, N_TOK, nullptr, rs, 1.f);

    gemm_nt<EPI_BIAS, false, false><<<gProj, blk, SMEM>>>(tmp, Wo, out_mean, N_TOK, DIM, DIM, bo, nullptr, 1.f);
}

// round 3
// speedup vs baseline: 1.8392x; 1.8392x over previous
#include <cuda_runtime.h>
#include <cstdint>

// ---------------------------------------------------------------------------
// UncertainTemporalAttention: N=8192 tokens, D=256.
//   q = 0.125*(x Wq^T + bq); k = x Wk^T + bk; v = x Wv^T + bv; vv = xv Wvar^T + bvar
//   P = exp(q k^T);  rowsum_i = sum_j P_ij
//   out_mean = ((P v)/rowsum) Wo^T + bo;  out_var = (P.^2 vv) / rowsum^2
// NT GEMMs (C = A * B^T, both K-contiguous). Plain tf32 mma with explicit
// cvt.rna (unbiased); QK^T uses a 2-term A-split for extra logit precision.
// N=256 GEMMs use TILE_N=64 (256 CTAs, 2 CTA/SM); QK^T uses TILE_N=128.
// ---------------------------------------------------------------------------

#define DEV_INLINE __device__ __forceinline__

constexpr int N_TOK = 8192;
constexpr int DIM   = 256;

__device__ float g_q  [N_TOK * DIM];
__device__ float g_k  [N_TOK * DIM];
__device__ float g_vT [DIM * N_TOK];
__device__ float g_vvT[DIM * N_TOK];
__device__ float g_tmp[N_TOK * DIM];
__device__ float g_rs [N_TOK];
__device__ float g_P  [(size_t)N_TOK * N_TOK];   // 256 MB

enum { EPI_BIAS = 0, EPI_EXP = 1, EPI_DIV = 2, EPI_DIV2 = 3 };

DEV_INLINE uint32_t smem_u32(const void* p) {
    return (uint32_t)__cvta_generic_to_shared(p);
}

DEV_INLINE void ldsm4(uint32_t* r, uint32_t a) {
    asm volatile("ldmatrix.sync.aligned.m8n8.x4.shared.b16 {%0,%1,%2,%3}, [%4];"
                 : "=r"(r[0]), "=r"(r[1]), "=r"(r[2]), "=r"(r[3]) : "r"(a));
}

DEV_INLINE void mma_tf32(float* c, const uint32_t* a, uint32_t b0, uint32_t b1) {
    asm volatile(
        "mma.sync.aligned.m16n8k8.row.col.f32.tf32.tf32.f32 "
        "{%0,%1,%2,%3},{%4,%5,%6,%7},{%8,%9},{%0,%1,%2,%3};"
        : "+f"(c[0]), "+f"(c[1]), "+f"(c[2]), "+f"(c[3])
        : "r"(a[0]), "r"(a[1]), "r"(a[2]), "r"(a[3]), "r"(b0), "r"(b1));
}

DEV_INLINE void cp16(uint32_t s, const void* g) {
    asm volatile("cp.async.cg.shared.global [%0], [%1], 16;" :: "r"(s), "l"(g));
}

DEV_INLINE uint32_t cvt_rna(float f) {
    uint32_t r;
    asm("cvt.rna.tf32.f32 %0, %1;" : "=r"(r) : "f"(f));
    return r;
}

// C[M,N] = epilogue( A[M,K] * B[N,K]^T )
// CTA tile 128 x TILE_N, K-chunk 32, 256 threads (2x4 warps).
// TILE_N=128: warp tile 64x32; TILE_N=64: warp tile 64x16 (2 CTAs/SM).
template <int EPI, bool SQA, bool TRANS, int TILE_N, bool SPLIT_A>
__global__ void __launch_bounds__(256, TILE_N == 64 ? 2 : 1)
gemm_nt(const float* __restrict__ A, const float* __restrict__ B,
        float* __restrict__ C, int M, int N, int K,
        const float* __restrict__ bias, const float* __restrict__ rowsum,
        float outScale)
{
    constexpr int NT      = TILE_N / 32;       // n-subtiles per warp (4 or 2)
    constexpr int P_CNT   = TILE_N / 64;       // B ldsm groups (2 or 1)
    constexpr int WN_COLS = TILE_N / 4;        // cols per warp (32 or 16)
    constexpr uint32_t B_BYTES = TILE_N * 128; // B stage bytes
    constexpr uint32_t STAGE   = 16384 + B_BYTES;

    extern __shared__ char smem_raw[];
    const uint32_t s_base = smem_u32(smem_raw);

    const int tid  = threadIdx.x;
    const int warp = tid >> 5, lane = tid & 31;
    const int wm = warp >> 2, wn = warp & 3;
    const int bm = blockIdx.y, bn = blockIdx.x;

    const float* Ab = A + (size_t)bm * 128 * K;
    const float* Bb = B + (size_t)bn * TILE_N * K;

    float c[4][NT][4];
#pragma unroll
    for (int i = 0; i < 4; i++)
#pragma unroll
        for (int j = 0; j < NT; j++)
#pragma unroll
            for (int l = 0; l < 4; l++) c[i][j][l] = 0.f;

    auto issue = [&](int stage, int kc) {
        const uint32_t sA = s_base + (uint32_t)stage * STAGE;
        const uint32_t sB = sA + 16384u;
        const int k0 = kc * 32;
#pragma unroll
        for (int i = 0; i < 4; i++) {           // A: 1024 float4
            int v = tid + i * 256;
            int row = v >> 3, ch = v & 7;
            uint32_t off = (uint32_t)(row * 128 + ((ch ^ (row & 7)) << 4));
            cp16(sA + off, Ab + (size_t)row * K + k0 + ch * 4);
        }
#pragma unroll
        for (int i = 0; i < TILE_N / 32; i++) { // B: TILE_N*8 float4
            int v = tid + i * 256;
            int row = v >> 3, ch = v & 7;
            uint32_t off = (uint32_t)(row * 128 + ((ch ^ (row & 7)) << 4));
            cp16(sB + off, Bb + (size_t)row * K + k0 + ch * 4);
        }
        asm volatile("cp.async.commit_group;");
    };

    auto compute = [&](int stage) {
        const uint32_t sA = s_base + (uint32_t)stage * STAGE;
        const uint32_t sB = sA + 16384u;
        const int lg = lane >> 3, li = lane & 7;
#pragma unroll
        for (int s8 = 0; s8 < 4; s8++) {
            uint32_t ah[4][4], al[4][4];
#pragma unroll
            for (int mt = 0; mt < 4; mt++) {
                uint32_t a[4];
                int row = wm * 64 + mt * 16 + (lg & 1) * 8 + li;
                int ch  = s8 * 2 + (lg >> 1);
                ldsm4(a, sA + row * 128 + ((ch ^ (row & 7)) << 4));
#pragma unroll
                for (int q = 0; q < 4; q++) {
                    float f = __uint_as_float(a[q]);
                    if (SQA) f *= f;
                    if (SPLIT_A) {
                        uint32_t hi = __float_as_uint(f) & 0xFFFFE000u; // exact trunc
                        ah[mt][q] = hi;
                        al[mt][q] = cvt_rna(f - __uint_as_float(hi));
                    } else {
                        ah[mt][q] = cvt_rna(f);
                    }
                }
            }
            uint32_t bh[P_CNT][4];
#pragma unroll
            for (int p = 0; p < P_CNT; p++) {
                uint32_t b[4];
                int row = wn * WN_COLS + p * 16 + (lg >> 1) * 8 + li;
                int ch  = s8 * 2 + (lg & 1);
                ldsm4(b, sB + row * 128 + ((ch ^ (row & 7)) << 4));
#pragma unroll
                for (int q = 0; q < 4; q++)
                    bh[p][q] = cvt_rna(__uint_as_float(b[q]));
            }
#pragma unroll
            for (int mt = 0; mt < 4; mt++)
#pragma unroll
                for (int nt = 0; nt < NT; nt++) {
                    const int p = nt >> 1, o = (nt & 1) * 2;
                    mma_tf32(c[mt][nt], ah[mt], bh[p][o], bh[p][o + 1]);
                    if (SPLIT_A)
                        mma_tf32(c[mt][nt], al[mt], bh[p][o], bh[p][o + 1]);
                }
        }
    };

    const int nk = K >> 5;
    issue(0, 0);
    for (int kc = 0; kc < nk; kc++) {
        if (kc + 1 < nk) {
            issue((kc + 1) & 1, kc + 1);
            asm volatile("cp.async.wait_group 1;");
        } else {
            asm volatile("cp.async.wait_group 0;");
        }
        __syncthreads();
        compute(kc & 1);
        __syncthreads();
    }

    // --- epilogue ---
    const int gr0 = bm * 128 + wm * 64;
    const int gc0 = bn * TILE_N + wn * WN_COLS;
#pragma unroll
    for (int mt = 0; mt < 4; mt++) {
#pragma unroll
        for (int rr = 0; rr < 2; rr++) {
            int row = gr0 + mt * 16 + rr * 8 + (lane >> 2);
            float rfac = 1.f;
            if (EPI == EPI_DIV)  rfac = 1.f / rowsum[row];
            if (EPI == EPI_DIV2) { float s = rowsum[row]; rfac = 1.f / (s * s); }
#pragma unroll
            for (int nt = 0; nt < NT; nt++) {
                int col = gc0 + nt * 8 + (lane & 3) * 2;
                float v0 = c[mt][nt][rr * 2 + 0];
                float v1 = c[mt][nt][rr * 2 + 1];
                if (EPI == EPI_BIAS) {
                    v0 = (v0 + bias[col])     * outScale;
                    v1 = (v1 + bias[col + 1]) * outScale;
                } else if (EPI == EPI_EXP) {
                    v0 = __expf(v0); v1 = __expf(v1);
                } else {
                    v0 *= rfac; v1 *= rfac;
                }
                if (TRANS) {
                    C[(size_t)col * M + row]       = v0;
                    C[(size_t)(col + 1) * M + row] = v1;
                } else {
                    *reinterpret_cast<float2*>(&C[(size_t)row * N + col]) =
                        make_float2(v0, v1);
                }
            }
        }
    }
}

// rowsum over P, one block per row, deterministic (no atomics)
__global__ void rowsum_kernel(const float* __restrict__ P, float* __restrict__ rs)
{
    const int row = blockIdx.x;
    const float4* p = reinterpret_cast<const float4*>(P + (size_t)row * N_TOK);
    float s = 0.f;
    for (int i = threadIdx.x; i < N_TOK / 4; i += 256) {
        float4 v = p[i];
        s += (v.x + v.y) + (v.z + v.w);
    }
#pragma unroll
    for (int o = 16; o > 0; o >>= 1) s += __shfl_xor_sync(0xffffffffu, s, o);
    __shared__ float ws[8];
    if ((threadIdx.x & 31) == 0) ws[threadIdx.x >> 5] = s;
    __syncthreads();
    if (threadIdx.x == 0) {
        float t = 0.f;
#pragma unroll
        for (int w = 0; w < 8; w++) t += ws[w];
        rs[row] = t;
    }
}

extern "C" void kernel_launch(void* const* d_in, const int* in_sizes, int n_in,
                              void* d_out, int out_size)
{
    (void)in_sizes; (void)n_in; (void)out_size;
    const float* x_mean = (const float*)d_in[0];
    const float* x_var  = (const float*)d_in[1];
    // d_in[2]=edge_index (unused), d_in[3]=edge_timestamps (unused)
    const float* Wq = (const float*)d_in[4];  const float* bq = (const float*)d_in[5];
    const float* Wk = (const float*)d_in[6];  const float* bk = (const float*)d_in[7];
    const float* Wv = (const float*)d_in[8];  const float* bv = (const float*)d_in[9];
    const float* Wo = (const float*)d_in[10]; const float* bo = (const float*)d_in[11];
    const float* Wvar = (const float*)d_in[12]; const float* bvar = (const float*)d_in[13];

    float* out_mean = (float*)d_out;
    float* out_var  = out_mean + (size_t)N_TOK * DIM;

    float *q, *k, *vT, *vvT, *tmp, *P, *rs;
    cudaGetSymbolAddress((void**)&q,   g_q);
    cudaGetSymbolAddress((void**)&k,   g_k);
    cudaGetSymbolAddress((void**)&vT,  g_vT);
    cudaGetSymbolAddress((void**)&vvT, g_vvT);
    cudaGetSymbolAddress((void**)&tmp, g_tmp);
    cudaGetSymbolAddress((void**)&P,   g_P);
    cudaGetSymbolAddress((void**)&rs,  g_rs);

    const int SMEM64  = 49152;   // TILE_N=64: (16K + 8K) * 2 stages
    const int SMEM128 = 65536;   // TILE_N=128

    cudaFuncSetAttribute((const void*)gemm_nt<EPI_BIAS, false, false, 64, false>, cudaFuncAttributeMaxDynamicSharedMemorySize, SMEM64);
    cudaFuncSetAttribute((const void*)gemm_nt<EPI_BIAS, false, true,  64, false>, cudaFuncAttributeMaxDynamicSharedMemorySize, SMEM64);
    cudaFuncSetAttribute((const void*)gemm_nt<EPI_EXP,  false, false, 128, true>, cudaFuncAttributeMaxDynamicSharedMemorySize, SMEM128);
    cudaFuncSetAttribute((const void*)gemm_nt<EPI_DIV,  false, false, 64, false>, cudaFuncAttributeMaxDynamicSharedMemorySize, SMEM64);
    cudaFuncSetAttribute((const void*)gemm_nt<EPI_DIV2, true,  false, 64, false>, cudaFuncAttributeMaxDynamicSharedMemorySize, SMEM64);

    dim3 blk(256);
    dim3 gProj(DIM / 64, N_TOK / 128);      // (4, 64)  = 256 CTAs
    dim3 gAttn(N_TOK / 128, N_TOK / 128);   // (64, 64) = 4096 CTAs

    // projections (scale 0.125 folded into q); v / v_var stored transposed
    gemm_nt<EPI_BIAS, false, false, 64, false><<<gProj, blk, SMEM64>>>(x_mean, Wq,   q,   N_TOK, DIM, DIM, bq,   nullptr, 0.125f);
    gemm_nt<EPI_BIAS, false, false, 64, false><<<gProj, blk, SMEM64>>>(x_mean, Wk,   k,   N_TOK, DIM, DIM, bk,   nullptr, 1.f);
    gemm_nt<EPI_BIAS, false, true,  64, false><<<gProj, blk, SMEM64>>>(x_mean, Wv,   vT,  N_TOK, DIM, DIM, bv,   nullptr, 1.f);
    gemm_nt<EPI_BIAS, false, true,  64, false><<<gProj, blk, SMEM64>>>(x_var,  Wvar, vvT, N_TOK, DIM, DIM, bvar, nullptr, 1.f);

    // P = exp(q k^T)   (A-split for logit precision)
    gemm_nt<EPI_EXP, false, false, 128, true><<<gAttn, blk, SMEM128>>>(q, k, P, N_TOK, N_TOK, DIM, nullptr, nullptr, 1.f);

    rowsum_kernel<<<N_TOK, 256>>>(P, rs);

    // tmp = (P @ v) / rowsum ; out_var = (P^2 @ v_var) / rowsum^2
    gemm_nt<EPI_DIV,  false, false, 64, false><<<gProj, blk, SMEM64>>>(P, vT,  tmp,     N_TOK, DIM, N_TOK, nullptr, rs, 1.f);
    gemm_nt<EPI_DIV2, true,  false, 64, false><<<gProj, blk, SMEM64>>>(P, vvT, out_var, N_TOK, DIM, N_TOK, nullptr, rs, 1.f);

    // out_mean = tmp @ Wo^T + bo
    gemm_nt<EPI_BIAS, false, false, 64, false><<<gProj, blk, SMEM64>>>(tmp, Wo, out_mean, N_TOK, DIM, DIM, bo, nullptr, 1.f);
}

// round 4
// speedup vs baseline: 2.9315x; 1.5939x over previous
#include <cuda_runtime.h>
#include <cstdint>

// ---------------------------------------------------------------------------
// UncertainTemporalAttention: N=8192, D=256.
//   q = 0.125*(x Wq^T + bq); k = x Wk^T + bk; v = x Wv^T + bv; vv = xv Wvar^T + bvar
//   P = exp(q k^T);  rs_i = sum_j P_ij
//   out_mean = ((P v)/rs) Wo^T + bo;  out_var = (P.^2 vv) / rs^2
// All GEMMs NT, tf32 mma.sync. Producers pre-round outputs to tf32 (cvt.rna)
// so big-GEMM mainloops are cvt-free. PV and P^2 VV fused (P read once).
// Rowsum folded into QK^T epilogue partials.
// ---------------------------------------------------------------------------

#define DEV_INLINE __device__ __forceinline__

constexpr int N_TOK = 8192;
constexpr int DIM   = 256;

__device__ float g_q  [N_TOK * DIM];
__device__ float g_k  [N_TOK * DIM];
__device__ float g_vT [DIM * N_TOK];
__device__ float g_vvT[DIM * N_TOK];
__device__ float g_tmp[N_TOK * DIM];
__device__ float g_rs [N_TOK];
__device__ float g_rsp[64 * N_TOK];              // rowsum partials (per bn)
__device__ float g_P  [(size_t)N_TOK * N_TOK];   // 256 MB

DEV_INLINE uint32_t smem_u32(const void* p) {
    return (uint32_t)__cvta_generic_to_shared(p);
}
DEV_INLINE void ldsm4(uint32_t* r, uint32_t a) {
    asm volatile("ldmatrix.sync.aligned.m8n8.x4.shared.b16 {%0,%1,%2,%3}, [%4];"
                 : "=r"(r[0]), "=r"(r[1]), "=r"(r[2]), "=r"(r[3]) : "r"(a));
}
DEV_INLINE void mma_tf32(float* c, const uint32_t* a, uint32_t b0, uint32_t b1) {
    asm volatile(
        "mma.sync.aligned.m16n8k8.row.col.f32.tf32.tf32.f32 "
        "{%0,%1,%2,%3},{%4,%5,%6,%7},{%8,%9},{%0,%1,%2,%3};"
        : "+f"(c[0]), "+f"(c[1]), "+f"(c[2]), "+f"(c[3])
        : "r"(a[0]), "r"(a[1]), "r"(a[2]), "r"(a[3]), "r"(b0), "r"(b1));
}
DEV_INLINE void cp16(uint32_t s, const void* g) {
    asm volatile("cp.async.cg.shared.global [%0], [%1], 16;" :: "r"(s), "l"(g));
}
DEV_INLINE uint32_t cvt_rna(float f) {
    uint32_t r;
    asm("cvt.rna.tf32.f32 %0, %1;" : "=r"(r) : "f"(f));
    return r;
}
DEV_INLINE float round_tf32(float f) { return __uint_as_float(cvt_rna(f)); }

// ===========================================================================
// Projection GEMM: C = (A[M,256] * B[256,256]^T + bias) * scale
// CTA 128x64, 256 thr (2x4 warps), warp tile 64x16. blockIdx.z picks job.
// ===========================================================================
template <bool TRANS, bool ROUND_OUT, bool CVT_A>
__global__ void __launch_bounds__(256, 2)
proj_kernel(const float* __restrict__ A0, const float* __restrict__ B0,
            const float* __restrict__ bias0, float* __restrict__ C0, float scale0,
            const float* __restrict__ A1, const float* __restrict__ B1,
            const float* __restrict__ bias1, float* __restrict__ C1, float scale1,
            int M)
{
    const float* A    = blockIdx.z ? A1 : A0;
    const float* B    = blockIdx.z ? B1 : B0;
    const float* bias = blockIdx.z ? bias1 : bias0;
    float*       C    = blockIdx.z ? C1 : C0;
    const float scale = blockIdx.z ? scale1 : scale0;
    const int K = DIM, N = DIM;

    extern __shared__ char smem_raw[];
    const uint32_t s_base = smem_u32(smem_raw);
    const int tid = threadIdx.x;
    const int warp = tid >> 5, lane = tid & 31;
    const int wm = warp >> 2, wn = warp & 3;
    const int bm = blockIdx.y, bn = blockIdx.x;

    const float* Ab = A + (size_t)bm * 128 * K;
    const float* Bb = B + (size_t)bn * 64 * K;

    float c[4][2][4];
#pragma unroll
    for (int i = 0; i < 4; i++)
#pragma unroll
        for (int j = 0; j < 2; j++)
#pragma unroll
            for (int l = 0; l < 4; l++) c[i][j][l] = 0.f;

    auto issue = [&](int stage, int kc) {
        const uint32_t sA = s_base + (uint32_t)stage * 24576u;
        const uint32_t sB = sA + 16384u;
        const int k0 = kc * 32;
#pragma unroll
        for (int i = 0; i < 4; i++) {
            int v = tid + i * 256; int row = v >> 3, ch = v & 7;
            uint32_t off = (uint32_t)(row * 128 + ((ch ^ (row & 7)) << 4));
            cp16(sA + off, Ab + (size_t)row * K + k0 + ch * 4);
        }
#pragma unroll
        for (int i = 0; i < 2; i++) {
            int v = tid + i * 256; int row = v >> 3, ch = v & 7;
            uint32_t off = (uint32_t)(row * 128 + ((ch ^ (row & 7)) << 4));
            cp16(sB + off, Bb + (size_t)row * K + k0 + ch * 4);
        }
        asm volatile("cp.async.commit_group;");
    };

    auto compute = [&](int stage) {
        const uint32_t sA = s_base + (uint32_t)stage * 24576u;
        const uint32_t sB = sA + 16384u;
        const int lg = lane >> 3, li = lane & 7;
#pragma unroll
        for (int s8 = 0; s8 < 4; s8++) {
            uint32_t a[4][4];
#pragma unroll
            for (int mt = 0; mt < 4; mt++) {
                int row = wm * 64 + mt * 16 + (lg & 1) * 8 + li;
                int ch  = s8 * 2 + (lg >> 1);
                ldsm4(a[mt], sA + row * 128 + ((ch ^ (row & 7)) << 4));
                if (CVT_A) {
#pragma unroll
                    for (int q = 0; q < 4; q++)
                        a[mt][q] = cvt_rna(__uint_as_float(a[mt][q]));
                }
            }
            uint32_t b[4];
            {
                int row = wn * 16 + (lg >> 1) * 8 + li;
                int ch  = s8 * 2 + (lg & 1);
                ldsm4(b, sB + row * 128 + ((ch ^ (row & 7)) << 4));
#pragma unroll
                for (int q = 0; q < 4; q++)
                    b[q] = cvt_rna(__uint_as_float(b[q]));
            }
#pragma unroll
            for (int mt = 0; mt < 4; mt++)
#pragma unroll
                for (int nt = 0; nt < 2; nt++)
                    mma_tf32(c[mt][nt], a[mt], b[nt * 2], b[nt * 2 + 1]);
        }
    };

    const int nk = K >> 5;
    issue(0, 0);
    for (int kc = 0; kc < nk; kc++) {
        if (kc + 1 < nk) { issue((kc + 1) & 1, kc + 1); asm volatile("cp.async.wait_group 1;"); }
        else             { asm volatile("cp.async.wait_group 0;"); }
        __syncthreads();
        compute(kc & 1);
        __syncthreads();
    }

    const int gr0 = bm * 128 + wm * 64;
    const int gc0 = bn * 64 + wn * 16;
#pragma unroll
    for (int mt = 0; mt < 4; mt++)
#pragma unroll
        for (int rr = 0; rr < 2; rr++) {
            int row = gr0 + mt * 16 + rr * 8 + (lane >> 2);
#pragma unroll
            for (int nt = 0; nt < 2; nt++) {
                int col = gc0 + nt * 8 + (lane & 3) * 2;
                float v0 = (c[mt][nt][rr * 2 + 0] + bias[col])     * scale;
                float v1 = (c[mt][nt][rr * 2 + 1] + bias[col + 1]) * scale;
                if (ROUND_OUT) { v0 = round_tf32(v0); v1 = round_tf32(v1); }
                if (TRANS) {
                    C[(size_t)col * M + row]       = v0;
                    C[(size_t)(col + 1) * M + row] = v1;
                } else {
                    *reinterpret_cast<float2*>(&C[(size_t)row * N + col]) =
                        make_float2(v0, v1);
                }
            }
        }
}

// ===========================================================================
// QK^T + exp + rowsum partials. CTA 128x128, inputs pre-rounded (no cvt).
// ===========================================================================
__global__ void __launch_bounds__(256, 2)
qk_exp_kernel(const float* __restrict__ Q, const float* __restrict__ Km,
              float* __restrict__ P, float* __restrict__ rsp)
{
    const int K = DIM;
    extern __shared__ char smem_raw[];
    const uint32_t s_base = smem_u32(smem_raw);
    __shared__ float rsum[4][128];

    const int tid = threadIdx.x;
    const int warp = tid >> 5, lane = tid & 31;
    const int wm = warp >> 2, wn = warp & 3;
    const int bm = blockIdx.y, bn = blockIdx.x;

    const float* Ab = Q + (size_t)bm * 128 * K;
    const float* Bb = Km + (size_t)bn * 128 * K;

    float c[4][4][4];
#pragma unroll
    for (int i = 0; i < 4; i++)
#pragma unroll
        for (int j = 0; j < 4; j++)
#pragma unroll
            for (int l = 0; l < 4; l++) c[i][j][l] = 0.f;

    auto issue = [&](int stage, int kc) {
        const uint32_t sA = s_base + (uint32_t)stage * 32768u;
        const uint32_t sB = sA + 16384u;
        const int k0 = kc * 32;
#pragma unroll
        for (int i = 0; i < 4; i++) {
            int v = tid + i * 256; int row = v >> 3, ch = v & 7;
            uint32_t off = (uint32_t)(row * 128 + ((ch ^ (row & 7)) << 4));
            cp16(sA + off, Ab + (size_t)row * K + k0 + ch * 4);
            cp16(sB + off, Bb + (size_t)row * K + k0 + ch * 4);
        }
        asm volatile("cp.async.commit_group;");
    };

    auto compute = [&](int stage) {
        const uint32_t sA = s_base + (uint32_t)stage * 32768u;
        const uint32_t sB = sA + 16384u;
        const int lg = lane >> 3, li = lane & 7;
#pragma unroll
        for (int s8 = 0; s8 < 4; s8++) {
            uint32_t a[4][4];
#pragma unroll
            for (int mt = 0; mt < 4; mt++) {
                int row = wm * 64 + mt * 16 + (lg & 1) * 8 + li;
                int ch  = s8 * 2 + (lg >> 1);
                ldsm4(a[mt], sA + row * 128 + ((ch ^ (row & 7)) << 4));
            }
            uint32_t b[2][4];
#pragma unroll
            for (int p = 0; p < 2; p++) {
                int row = wn * 32 + p * 16 + (lg >> 1) * 8 + li;
                int ch  = s8 * 2 + (lg & 1);
                ldsm4(b[p], sB + row * 128 + ((ch ^ (row & 7)) << 4));
            }
#pragma unroll
            for (int mt = 0; mt < 4; mt++)
#pragma unroll
                for (int nt = 0; nt < 4; nt++)
                    mma_tf32(c[mt][nt], a[mt],
                             b[nt >> 1][(nt & 1) * 2], b[nt >> 1][(nt & 1) * 2 + 1]);
        }
    };

    const int nk = K >> 5;
    issue(0, 0);
    for (int kc = 0; kc < nk; kc++) {
        if (kc + 1 < nk) { issue((kc + 1) & 1, kc + 1); asm volatile("cp.async.wait_group 1;"); }
        else             { asm volatile("cp.async.wait_group 0;"); }
        __syncthreads();
        compute(kc & 1);
        __syncthreads();
    }

    // epilogue: exp, rowsum partials, rounded store
    const int gr0 = bm * 128 + wm * 64;
    const int gc0 = bn * 128 + wn * 32;
#pragma unroll
    for (int mt = 0; mt < 4; mt++)
#pragma unroll
        for (int rr = 0; rr < 2; rr++) {
            int row = gr0 + mt * 16 + rr * 8 + (lane >> 2);
            float rowpart = 0.f;
#pragma unroll
            for (int nt = 0; nt < 4; nt++) {
                int col = gc0 + nt * 8 + (lane & 3) * 2;
                float v0 = __expf(c[mt][nt][rr * 2 + 0]);
                float v1 = __expf(c[mt][nt][rr * 2 + 1]);
                rowpart += v0 + v1;
                *reinterpret_cast<float2*>(&P[(size_t)row * N_TOK + col]) =
                    make_float2(round_tf32(v0), round_tf32(v1));
            }
            rowpart += __shfl_xor_sync(0xffffffffu, rowpart, 1);
            rowpart += __shfl_xor_sync(0xffffffffu, rowpart, 2);
            if ((lane & 3) == 0)
                rsum[wn][wm * 64 + mt * 16 + rr * 8 + (lane >> 2)] = rowpart;
        }
    __syncthreads();
    if (tid < 128) {
        float s = rsum[0][tid] + rsum[1][tid] + rsum[2][tid] + rsum[3][tid];
        rsp[(size_t)bn * N_TOK + bm * 128 + tid] = s;
    }
}

__global__ void rs_reduce_kernel(const float* __restrict__ rsp, float* __restrict__ rs)
{
    int row = blockIdx.x * 256 + threadIdx.x;
    float s = 0.f;
#pragma unroll 8
    for (int bn = 0; bn < 64; bn++) s += rsp[(size_t)bn * N_TOK + row];
    rs[row] = s;
}

// ===========================================================================
// Fused: tmp = (P vT^T)/rs  and  out_var = (P.^2 vvT^T)/rs^2.
// CTA 128x64, dual accumulators. P pre-rounded tf32.
// ===========================================================================
__global__ void __launch_bounds__(256, 2)
fused_pv_kernel(const float* __restrict__ P, const float* __restrict__ vT,
                const float* __restrict__ vvT, const float* __restrict__ rs,
                float* __restrict__ tmp, float* __restrict__ out_var)
{
    const int K = N_TOK;
    extern __shared__ char smem_raw[];
    const uint32_t s_base = smem_u32(smem_raw);   // stage: A 16K | B1 8K | B2 8K
    const int tid = threadIdx.x;
    const int warp = tid >> 5, lane = tid & 31;
    const int wm = warp >> 2, wn = warp & 3;
    const int bm = blockIdx.y, bn = blockIdx.x;

    const float* Ab  = P   + (size_t)bm * 128 * K;
    const float* B1b = vT  + (size_t)bn * 64 * K;
    const float* B2b = vvT + (size_t)bn * 64 * K;

    float cm[4][2][4], cv[4][2][4];
#pragma unroll
    for (int i = 0; i < 4; i++)
#pragma unroll
        for (int j = 0; j < 2; j++)
#pragma unroll
            for (int l = 0; l < 4; l++) { cm[i][j][l] = 0.f; cv[i][j][l] = 0.f; }

    auto issue = [&](int stage, int kc) {
        const uint32_t sA = s_base + (uint32_t)stage * 32768u;
        const uint32_t sB1 = sA + 16384u;
        const uint32_t sB2 = sB1 + 8192u;
        const int k0 = kc * 32;
#pragma unroll
        for (int i = 0; i < 4; i++) {
            int v = tid + i * 256; int row = v >> 3, ch = v & 7;
            uint32_t off = (uint32_t)(row * 128 + ((ch ^ (row & 7)) << 4));
            cp16(sA + off, Ab + (size_t)row * K + k0 + ch * 4);
        }
#pragma unroll
        for (int i = 0; i < 2; i++) {
            int v = tid + i * 256; int row = v >> 3, ch = v & 7;
            uint32_t off = (uint32_t)(row * 128 + ((ch ^ (row & 7)) << 4));
            cp16(sB1 + off, B1b + (size_t)row * K + k0 + ch * 4);
            cp16(sB2 + off, B2b + (size_t)row * K + k0 + ch * 4);
        }
        asm volatile("cp.async.commit_group;");
    };

    auto compute = [&](int stage) {
        const uint32_t sA = s_base + (uint32_t)stage * 32768u;
        const uint32_t sB1 = sA + 16384u;
        const uint32_t sB2 = sB1 + 8192u;
        const int lg = lane >> 3, li = lane & 7;
#pragma unroll
        for (int s8 = 0; s8 < 4; s8++) {
            uint32_t a[4][4];
#pragma unroll
            for (int mt = 0; mt < 4; mt++) {
                int row = wm * 64 + mt * 16 + (lg & 1) * 8 + li;
                int ch  = s8 * 2 + (lg >> 1);
                ldsm4(a[mt], sA + row * 128 + ((ch ^ (row & 7)) << 4));
            }
            uint32_t b1[4], b2[4];
            {
                int row = wn * 16 + (lg >> 1) * 8 + li;
                int ch  = s8 * 2 + (lg & 1);
                ldsm4(b1, sB1 + row * 128 + ((ch ^ (row & 7)) << 4));
                ldsm4(b2, sB2 + row * 128 + ((ch ^ (row & 7)) << 4));
            }
#pragma unroll
            for (int mt = 0; mt < 4; mt++)
#pragma unroll
                for (int nt = 0; nt < 2; nt++)
                    mma_tf32(cm[mt][nt], a[mt], b1[nt * 2], b1[nt * 2 + 1]);
            // square A in place (pre-rounded tf32 -> one cvt after mul)
#pragma unroll
            for (int mt = 0; mt < 4; mt++)
#pragma unroll
                for (int q = 0; q < 4; q++) {
                    float f = __uint_as_float(a[mt][q]);
                    a[mt][q] = cvt_rna(f * f);
                }
#pragma unroll
            for (int mt = 0; mt < 4; mt++)
#pragma unroll
                for (int nt = 0; nt < 2; nt++)
                    mma_tf32(cv[mt][nt], a[mt], b2[nt * 2], b2[nt * 2 + 1]);
        }
    };

    const int nk = K >> 5;
    issue(0, 0);
    for (int kc = 0; kc < nk; kc++) {
        if (kc + 1 < nk) { issue((kc + 1) & 1, kc + 1); asm volatile("cp.async.wait_group 1;"); }
        else             { asm volatile("cp.async.wait_group 0;"); }
        __syncthreads();
        compute(kc & 1);
        __syncthreads();
    }

    const int gr0 = bm * 128 + wm * 64;
    const int gc0 = bn * 64 + wn * 16;
#pragma unroll
    for (int mt = 0; mt < 4; mt++)
#pragma unroll
        for (int rr = 0; rr < 2; rr++) {
            int row = gr0 + mt * 16 + rr * 8 + (lane >> 2);
            float rfac = 1.f / rs[row];
            float rfac2 = rfac * rfac;
#pragma unroll
            for (int nt = 0; nt < 2; nt++) {
                int col = gc0 + nt * 8 + (lane & 3) * 2;
                float m0 = cm[mt][nt][rr * 2 + 0] * rfac;
                float m1 = cm[mt][nt][rr * 2 + 1] * rfac;
                *reinterpret_cast<float2*>(&tmp[(size_t)row * DIM + col]) =
                    make_float2(round_tf32(m0), round_tf32(m1));
                float v0 = cv[mt][nt][rr * 2 + 0] * rfac2;
                float v1 = cv[mt][nt][rr * 2 + 1] * rfac2;
                *reinterpret_cast<float2*>(&out_var[(size_t)row * DIM + col]) =
                    make_float2(v0, v1);
            }
        }
}

// ===========================================================================
extern "C" void kernel_launch(void* const* d_in, const int* in_sizes, int n_in,
                              void* d_out, int out_size)
{
    (void)in_sizes; (void)n_in; (void)out_size;
    const float* x_mean = (const float*)d_in[0];
    const float* x_var  = (const float*)d_in[1];
    const float* Wq = (const float*)d_in[4];  const float* bq = (const float*)d_in[5];
    const float* Wk = (const float*)d_in[6];  const float* bk = (const float*)d_in[7];
    const float* Wv = (const float*)d_in[8];  const float* bv = (const float*)d_in[9];
    const float* Wo = (const float*)d_in[10]; const float* bo = (const float*)d_in[11];
    const float* Wvar = (const float*)d_in[12]; const float* bvar = (const float*)d_in[13];

    float* out_mean = (float*)d_out;
    float* out_var  = out_mean + (size_t)N_TOK * DIM;

    float *q, *k, *vT, *vvT, *tmp, *P, *rs, *rsp;
    cudaGetSymbolAddress((void**)&q,   g_q);
    cudaGetSymbolAddress((void**)&k,   g_k);
    cudaGetSymbolAddress((void**)&vT,  g_vT);
    cudaGetSymbolAddress((void**)&vvT, g_vvT);
    cudaGetSymbolAddress((void**)&tmp, g_tmp);
    cudaGetSymbolAddress((void**)&P,   g_P);
    cudaGetSymbolAddress((void**)&rs,  g_rs);
    cudaGetSymbolAddress((void**)&rsp, g_rsp);

    const int SM_PROJ = 49152;   // (16K+8K)*2
    const int SM_QK   = 65536;   // (16K+16K)*2
    const int SM_PV   = 65536;   // (16K+8K+8K)*2

    cudaFuncSetAttribute((const void*)proj_kernel<false, true,  true >, cudaFuncAttributeMaxDynamicSharedMemorySize, SM_PROJ);
    cudaFuncSetAttribute((const void*)proj_kernel<true,  true,  true >, cudaFuncAttributeMaxDynamicSharedMemorySize, SM_PROJ);
    cudaFuncSetAttribute((const void*)proj_kernel<false, false, false>, cudaFuncAttributeMaxDynamicSharedMemorySize, SM_PROJ);
    cudaFuncSetAttribute((const void*)qk_exp_kernel,   cudaFuncAttributeMaxDynamicSharedMemorySize, SM_QK);
    cudaFuncSetAttribute((const void*)fused_pv_kernel, cudaFuncAttributeMaxDynamicSharedMemorySize, SM_PV);

    dim3 blk(256);
    dim3 gProj2(DIM / 64, N_TOK / 128, 2);  // (4, 64, 2)
    dim3 gProj1(DIM / 64, N_TOK / 128, 1);
    dim3 gAttn(N_TOK / 128, N_TOK / 128);   // (64, 64)

    // q (scale 0.125) and k in one launch; vT and vvT (transposed) in another
    proj_kernel<false, true, true><<<gProj2, blk, SM_PROJ>>>(
        x_mean, Wq, bq, q, 0.125f,  x_mean, Wk, bk, k, 1.f, N_TOK);
    proj_kernel<true, true, true><<<gProj2, blk, SM_PROJ>>>(
        x_mean, Wv, bv, vT, 1.f,    x_var, Wvar, bvar, vvT, 1.f, N_TOK);

    qk_exp_kernel<<<gAttn, blk, SM_QK>>>(q, k, P, rsp);
    rs_reduce_kernel<<<N_TOK / 256, 256>>>(rsp, rs);

    fused_pv_kernel<<<gProj1, blk, SM_PV>>>(P, vT, vvT, rs, tmp, out_var);

    proj_kernel<false, false, false><<<gProj1, blk, SM_PROJ>>>(
        tmp, Wo, bo, out_mean, 1.f, tmp, Wo, bo, out_mean, 1.f, N_TOK);
}

// round 6
// speedup vs baseline: 2.9329x; 1.0005x over previous
#include <cuda_runtime.h>
#include <cstdint>

// ---------------------------------------------------------------------------
// UncertainTemporalAttention: N=8192, D=256.
//   q = 0.125*(x Wq^T + bq); k = x Wk^T + bk; v = x Wv^T + bv; vv = xv Wvar^T + bvar
//   P = exp(q k^T);  rs_i = sum_j P_ij
//   out_mean = ((P v)/rs) Wo^T + bo;  out_var = (P.^2 vv) / rs^2
// All GEMMs NT, tf32 mma.sync. Producers pre-round outputs to tf32 (cvt.rna)
// so big-GEMM mainloops are cvt-free. PV and P^2 VV fused (P read once).
// Rowsum folded into QK^T epilogue partials.
// ---------------------------------------------------------------------------

#define DEV_INLINE __device__ __forceinline__

constexpr int N_TOK = 8192;
constexpr int DIM   = 256;

__device__ float g_q  [N_TOK * DIM];
__device__ float g_k  [N_TOK * DIM];
__device__ float g_vT [DIM * N_TOK];
__device__ float g_vvT[DIM * N_TOK];
__device__ float g_tmp[N_TOK * DIM];
__device__ float g_rs [N_TOK];
__device__ float g_rsp[64 * N_TOK];              // rowsum partials (per bn)
__device__ float g_P  [(size_t)N_TOK * N_TOK];   // 256 MB

DEV_INLINE uint32_t smem_u32(const void* p) {
    return (uint32_t)__cvta_generic_to_shared(p);
}
DEV_INLINE void ldsm4(uint32_t* r, uint32_t a) {
    asm volatile("ldmatrix.sync.aligned.m8n8.x4.shared.b16 {%0,%1,%2,%3}, [%4];"
                 : "=r"(r[0]), "=r"(r[1]), "=r"(r[2]), "=r"(r[3]) : "r"(a));
}
DEV_INLINE void mma_tf32(float* c, const uint32_t* a, uint32_t b0, uint32_t b1) {
    asm volatile(
        "mma.sync.aligned.m16n8k8.row.col.f32.tf32.tf32.f32 "
        "{%0,%1,%2,%3},{%4,%5,%6,%7},{%8,%9},{%0,%1,%2,%3};"
        : "+f"(c[0]), "+f"(c[1]), "+f"(c[2]), "+f"(c[3])
        : "r"(a[0]), "r"(a[1]), "r"(a[2]), "r"(a[3]), "r"(b0), "r"(b1));
}
DEV_INLINE void cp16(uint32_t s, const void* g) {
    asm volatile("cp.async.cg.shared.global [%0], [%1], 16;" :: "r"(s), "l"(g));
}
DEV_INLINE uint32_t cvt_rna(float f) {
    uint32_t r;
    asm("cvt.rna.tf32.f32 %0, %1;" : "=r"(r) : "f"(f));
    return r;
}
DEV_INLINE float round_tf32(float f) { return __uint_as_float(cvt_rna(f)); }

// ===========================================================================
// Projection GEMM: C = (A[M,256] * B[256,256]^T + bias) * scale
// CTA 128x64, 256 thr (2x4 warps), warp tile 64x16. blockIdx.z picks job.
// ===========================================================================
template <bool TRANS, bool ROUND_OUT, bool CVT_A>
__global__ void __launch_bounds__(256, 2)
proj_kernel(const float* __restrict__ A0, const float* __restrict__ B0,
            const float* __restrict__ bias0, float* __restrict__ C0, float scale0,
            const float* __restrict__ A1, const float* __restrict__ B1,
            const float* __restrict__ bias1, float* __restrict__ C1, float scale1,
            int M)
{
    const float* A    = blockIdx.z ? A1 : A0;
    const float* B    = blockIdx.z ? B1 : B0;
    const float* bias = blockIdx.z ? bias1 : bias0;
    float*       C    = blockIdx.z ? C1 : C0;
    const float scale = blockIdx.z ? scale1 : scale0;
    const int K = DIM, N = DIM;

    extern __shared__ char smem_raw[];
    const uint32_t s_base = smem_u32(smem_raw);
    const int tid = threadIdx.x;
    const int warp = tid >> 5, lane = tid & 31;
    const int wm = warp >> 2, wn = warp & 3;
    const int bm = blockIdx.y, bn = blockIdx.x;

    const float* Ab = A + (size_t)bm * 128 * K;
    const float* Bb = B + (size_t)bn * 64 * K;

    float c[4][2][4];
#pragma unroll
    for (int i = 0; i < 4; i++)
#pragma unroll
        for (int j = 0; j < 2; j++)
#pragma unroll
            for (int l = 0; l < 4; l++) c[i][j][l] = 0.f;

    auto issue = [&](int stage, int kc) {
        const uint32_t sA = s_base + (uint32_t)stage * 24576u;
        const uint32_t sB = sA + 16384u;
        const int k0 = kc * 32;
#pragma unroll
        for (int i = 0; i < 4; i++) {
            int v = tid + i * 256; int row = v >> 3, ch = v & 7;
            uint32_t off = (uint32_t)(row * 128 + ((ch ^ (row & 7)) << 4));
            cp16(sA + off, Ab + (size_t)row * K + k0 + ch * 4);
        }
#pragma unroll
        for (int i = 0; i < 2; i++) {
            int v = tid + i * 256; int row = v >> 3, ch = v & 7;
            uint32_t off = (uint32_t)(row * 128 + ((ch ^ (row & 7)) << 4));
            cp16(sB + off, Bb + (size_t)row * K + k0 + ch * 4);
        }
        asm volatile("cp.async.commit_group;");
    };

    auto compute = [&](int stage) {
        const uint32_t sA = s_base + (uint32_t)stage * 24576u;
        const uint32_t sB = sA + 16384u;
        const int lg = lane >> 3, li = lane & 7;
#pragma unroll
        for (int s8 = 0; s8 < 4; s8++) {
            uint32_t a[4][4];
#pragma unroll
            for (int mt = 0; mt < 4; mt++) {
                int row = wm * 64 + mt * 16 + (lg & 1) * 8 + li;
                int ch  = s8 * 2 + (lg >> 1);
                ldsm4(a[mt], sA + row * 128 + ((ch ^ (row & 7)) << 4));
                if (CVT_A) {
#pragma unroll
                    for (int q = 0; q < 4; q++)
                        a[mt][q] = cvt_rna(__uint_as_float(a[mt][q]));
                }
            }
            uint32_t b[4];
            {
                int row = wn * 16 + (lg >> 1) * 8 + li;
                int ch  = s8 * 2 + (lg & 1);
                ldsm4(b, sB + row * 128 + ((ch ^ (row & 7)) << 4));
#pragma unroll
                for (int q = 0; q < 4; q++)
                    b[q] = cvt_rna(__uint_as_float(b[q]));
            }
#pragma unroll
            for (int mt = 0; mt < 4; mt++)
#pragma unroll
                for (int nt = 0; nt < 2; nt++)
                    mma_tf32(c[mt][nt], a[mt], b[nt * 2], b[nt * 2 + 1]);
        }
    };

    const int nk = K >> 5;
    issue(0, 0);
    for (int kc = 0; kc < nk; kc++) {
        if (kc + 1 < nk) { issue((kc + 1) & 1, kc + 1); asm volatile("cp.async.wait_group 1;"); }
        else             { asm volatile("cp.async.wait_group 0;"); }
        __syncthreads();
        compute(kc & 1);
        __syncthreads();
    }

    const int gr0 = bm * 128 + wm * 64;
    const int gc0 = bn * 64 + wn * 16;
#pragma unroll
    for (int mt = 0; mt < 4; mt++)
#pragma unroll
        for (int rr = 0; rr < 2; rr++) {
            int row = gr0 + mt * 16 + rr * 8 + (lane >> 2);
#pragma unroll
            for (int nt = 0; nt < 2; nt++) {
                int col = gc0 + nt * 8 + (lane & 3) * 2;
                float v0 = (c[mt][nt][rr * 2 + 0] + bias[col])     * scale;
                float v1 = (c[mt][nt][rr * 2 + 1] + bias[col + 1]) * scale;
                if (ROUND_OUT) { v0 = round_tf32(v0); v1 = round_tf32(v1); }
                if (TRANS) {
                    C[(size_t)col * M + row]       = v0;
                    C[(size_t)(col + 1) * M + row] = v1;
                } else {
                    *reinterpret_cast<float2*>(&C[(size_t)row * N + col]) =
                        make_float2(v0, v1);
                }
            }
        }
}

// ===========================================================================
// QK^T + exp + rowsum partials. CTA 128x128, inputs pre-rounded (no cvt).
// ===========================================================================
__global__ void __launch_bounds__(256, 2)
qk_exp_kernel(const float* __restrict__ Q, const float* __restrict__ Km,
              float* __restrict__ P, float* __restrict__ rsp)
{
    const int K = DIM;
    extern __shared__ char smem_raw[];
    const uint32_t s_base = smem_u32(smem_raw);
    __shared__ float rsum[4][128];

    const int tid = threadIdx.x;
    const int warp = tid >> 5, lane = tid & 31;
    const int wm = warp >> 2, wn = warp & 3;
    const int bm = blockIdx.y, bn = blockIdx.x;

    const float* Ab = Q + (size_t)bm * 128 * K;
    const float* Bb = Km + (size_t)bn * 128 * K;

    float c[4][4][4];
#pragma unroll
    for (int i = 0; i < 4; i++)
#pragma unroll
        for (int j = 0; j < 4; j++)
#pragma unroll
            for (int l = 0; l < 4; l++) c[i][j][l] = 0.f;

    auto issue = [&](int stage, int kc) {
        const uint32_t sA = s_base + (uint32_t)stage * 32768u;
        const uint32_t sB = sA + 16384u;
        const int k0 = kc * 32;
#pragma unroll
        for (int i = 0; i < 4; i++) {
            int v = tid + i * 256; int row = v >> 3, ch = v & 7;
            uint32_t off = (uint32_t)(row * 128 + ((ch ^ (row & 7)) << 4));
            cp16(sA + off, Ab + (size_t)row * K + k0 + ch * 4);
            cp16(sB + off, Bb + (size_t)row * K + k0 + ch * 4);
        }
        asm volatile("cp.async.commit_group;");
    };

    auto compute = [&](int stage) {
        const uint32_t sA = s_base + (uint32_t)stage * 32768u;
        const uint32_t sB = sA + 16384u;
        const int lg = lane >> 3, li = lane & 7;
#pragma unroll
        for (int s8 = 0; s8 < 4; s8++) {
            uint32_t a[4][4];
#pragma unroll
            for (int mt = 0; mt < 4; mt++) {
                int row = wm * 64 + mt * 16 + (lg & 1) * 8 + li;
                int ch  = s8 * 2 + (lg >> 1);
                ldsm4(a[mt], sA + row * 128 + ((ch ^ (row & 7)) << 4));
            }
            uint32_t b[2][4];
#pragma unroll
            for (int p = 0; p < 2; p++) {
                int row = wn * 32 + p * 16 + (lg >> 1) * 8 + li;
                int ch  = s8 * 2 + (lg & 1);
                ldsm4(b[p], sB + row * 128 + ((ch ^ (row & 7)) << 4));
            }
#pragma unroll
            for (int mt = 0; mt < 4; mt++)
#pragma unroll
                for (int nt = 0; nt < 4; nt++)
                    mma_tf32(c[mt][nt], a[mt],
                             b[nt >> 1][(nt & 1) * 2], b[nt >> 1][(nt & 1) * 2 + 1]);
        }
    };

    const int nk = K >> 5;
    issue(0, 0);
    for (int kc = 0; kc < nk; kc++) {
        if (kc + 1 < nk) { issue((kc + 1) & 1, kc + 1); asm volatile("cp.async.wait_group 1;"); }
        else             { asm volatile("cp.async.wait_group 0;"); }
        __syncthreads();
        compute(kc & 1);
        __syncthreads();
    }

    // epilogue: exp, rowsum partials, rounded store
    const int gr0 = bm * 128 + wm * 64;
    const int gc0 = bn * 128 + wn * 32;
#pragma unroll
    for (int mt = 0; mt < 4; mt++)
#pragma unroll
        for (int rr = 0; rr < 2; rr++) {
            int row = gr0 + mt * 16 + rr * 8 + (lane >> 2);
            float rowpart = 0.f;
#pragma unroll
            for (int nt = 0; nt < 4; nt++) {
                int col = gc0 + nt * 8 + (lane & 3) * 2;
                float v0 = __expf(c[mt][nt][rr * 2 + 0]);
                float v1 = __expf(c[mt][nt][rr * 2 + 1]);
                rowpart += v0 + v1;
                *reinterpret_cast<float2*>(&P[(size_t)row * N_TOK + col]) =
                    make_float2(round_tf32(v0), round_tf32(v1));
            }
            rowpart += __shfl_xor_sync(0xffffffffu, rowpart, 1);
            rowpart += __shfl_xor_sync(0xffffffffu, rowpart, 2);
            if ((lane & 3) == 0)
                rsum[wn][wm * 64 + mt * 16 + rr * 8 + (lane >> 2)] = rowpart;
        }
    __syncthreads();
    if (tid < 128) {
        float s = rsum[0][tid] + rsum[1][tid] + rsum[2][tid] + rsum[3][tid];
        rsp[(size_t)bn * N_TOK + bm * 128 + tid] = s;
    }
}

__global__ void rs_reduce_kernel(const float* __restrict__ rsp, float* __restrict__ rs)
{
    int row = blockIdx.x * 256 + threadIdx.x;
    float s = 0.f;
#pragma unroll 8
    for (int bn = 0; bn < 64; bn++) s += rsp[(size_t)bn * N_TOK + row];
    rs[row] = s;
}

// ===========================================================================
// Fused: tmp = (P vT^T)/rs  and  out_var = (P.^2 vvT^T)/rs^2.
// CTA 128x64, dual accumulators. P pre-rounded tf32.
// ===========================================================================
__global__ void __launch_bounds__(256, 2)
fused_pv_kernel(const float* __restrict__ P, const float* __restrict__ vT,
                const float* __restrict__ vvT, const float* __restrict__ rs,
                float* __restrict__ tmp, float* __restrict__ out_var)
{
    const int K = N_TOK;
    extern __shared__ char smem_raw[];
    const uint32_t s_base = smem_u32(smem_raw);   // stage: A 16K | B1 8K | B2 8K
    const int tid = threadIdx.x;
    const int warp = tid >> 5, lane = tid & 31;
    const int wm = warp >> 2, wn = warp & 3;
    const int bm = blockIdx.y, bn = blockIdx.x;

    const float* Ab  = P   + (size_t)bm * 128 * K;
    const float* B1b = vT  + (size_t)bn * 64 * K;
    const float* B2b = vvT + (size_t)bn * 64 * K;

    float cm[4][2][4], cv[4][2][4];
#pragma unroll
    for (int i = 0; i < 4; i++)
#pragma unroll
        for (int j = 0; j < 2; j++)
#pragma unroll
            for (int l = 0; l < 4; l++) { cm[i][j][l] = 0.f; cv[i][j][l] = 0.f; }

    auto issue = [&](int stage, int kc) {
        const uint32_t sA = s_base + (uint32_t)stage * 32768u;
        const uint32_t sB1 = sA + 16384u;
        const uint32_t sB2 = sB1 + 8192u;
        const int k0 = kc * 32;
#pragma unroll
        for (int i = 0; i < 4; i++) {
            int v = tid + i * 256; int row = v >> 3, ch = v & 7;
            uint32_t off = (uint32_t)(row * 128 + ((ch ^ (row & 7)) << 4));
            cp16(sA + off, Ab + (size_t)row * K + k0 + ch * 4);
        }
#pragma unroll
        for (int i = 0; i < 2; i++) {
            int v = tid + i * 256; int row = v >> 3, ch = v & 7;
            uint32_t off = (uint32_t)(row * 128 + ((ch ^ (row & 7)) << 4));
            cp16(sB1 + off, B1b + (size_t)row * K + k0 + ch * 4);
            cp16(sB2 + off, B2b + (size_t)row * K + k0 + ch * 4);
        }
        asm volatile("cp.async.commit_group;");
    };

    auto compute = [&](int stage) {
        const uint32_t sA = s_base + (uint32_t)stage * 32768u;
        const uint32_t sB1 = sA + 16384u;
        const uint32_t sB2 = sB1 + 8192u;
        const int lg = lane >> 3, li = lane & 7;
#pragma unroll
        for (int s8 = 0; s8 < 4; s8++) {
            uint32_t a[4][4];
#pragma unroll
            for (int mt = 0; mt < 4; mt++) {
                int row = wm * 64 + mt * 16 + (lg & 1) * 8 + li;
                int ch  = s8 * 2 + (lg >> 1);
                ldsm4(a[mt], sA + row * 128 + ((ch ^ (row & 7)) << 4));
            }
            uint32_t b1[4], b2[4];
            {
                int row = wn * 16 + (lg >> 1) * 8 + li;
                int ch  = s8 * 2 + (lg & 1);
                ldsm4(b1, sB1 + row * 128 + ((ch ^ (row & 7)) << 4));
                ldsm4(b2, sB2 + row * 128 + ((ch ^ (row & 7)) << 4));
            }
#pragma unroll
            for (int mt = 0; mt < 4; mt++)
#pragma unroll
                for (int nt = 0; nt < 2; nt++)
                    mma_tf32(cm[mt][nt], a[mt], b1[nt * 2], b1[nt * 2 + 1]);
            // square A in place (pre-rounded tf32 -> one cvt after mul)
#pragma unroll
            for (int mt = 0; mt < 4; mt++)
#pragma unroll
                for (int q = 0; q < 4; q++) {
                    float f = __uint_as_float(a[mt][q]);
                    a[mt][q] = cvt_rna(f * f);
                }
#pragma unroll
            for (int mt = 0; mt < 4; mt++)
#pragma unroll
                for (int nt = 0; nt < 2; nt++)
                    mma_tf32(cv[mt][nt], a[mt], b2[nt * 2], b2[nt * 2 + 1]);
        }
    };

    const int nk = K >> 5;
    issue(0, 0);
    for (int kc = 0; kc < nk; kc++) {
        if (kc + 1 < nk) { issue((kc + 1) & 1, kc + 1); asm volatile("cp.async.wait_group 1;"); }
        else             { asm volatile("cp.async.wait_group 0;"); }
        __syncthreads();
        compute(kc & 1);
        __syncthreads();
    }

    const int gr0 = bm * 128 + wm * 64;
    const int gc0 = bn * 64 + wn * 16;
#pragma unroll
    for (int mt = 0; mt < 4; mt++)
#pragma unroll
        for (int rr = 0; rr < 2; rr++) {
            int row = gr0 + mt * 16 + rr * 8 + (lane >> 2);
            float rfac = 1.f / rs[row];
            float rfac2 = rfac * rfac;
#pragma unroll
            for (int nt = 0; nt < 2; nt++) {
                int col = gc0 + nt * 8 + (lane & 3) * 2;
                float m0 = cm[mt][nt][rr * 2 + 0] * rfac;
                float m1 = cm[mt][nt][rr * 2 + 1] * rfac;
                *reinterpret_cast<float2*>(&tmp[(size_t)row * DIM + col]) =
                    make_float2(round_tf32(m0), round_tf32(m1));
                float v0 = cv[mt][nt][rr * 2 + 0] * rfac2;
                float v1 = cv[mt][nt][rr * 2 + 1] * rfac2;
                *reinterpret_cast<float2*>(&out_var[(size_t)row * DIM + col]) =
                    make_float2(v0, v1);
            }
        }
}

// ===========================================================================
extern "C" void kernel_launch(void* const* d_in, const int* in_sizes, int n_in,
                              void* d_out, int out_size)
{
    (void)in_sizes; (void)n_in; (void)out_size;
    const float* x_mean = (const float*)d_in[0];
    const float* x_var  = (const float*)d_in[1];
    const float* Wq = (const float*)d_in[4];  const float* bq = (const float*)d_in[5];
    const float* Wk = (const float*)d_in[6];  const float* bk = (const float*)d_in[7];
    const float* Wv = (const float*)d_in[8];  const float* bv = (const float*)d_in[9];
    const float* Wo = (const float*)d_in[10]; const float* bo = (const float*)d_in[11];
    const float* Wvar = (const float*)d_in[12]; const float* bvar = (const float*)d_in[13];

    float* out_mean = (float*)d_out;
    float* out_var  = out_mean + (size_t)N_TOK * DIM;

    float *q, *k, *vT, *vvT, *tmp, *P, *rs, *rsp;
    cudaGetSymbolAddress((void**)&q,   g_q);
    cudaGetSymbolAddress((void**)&k,   g_k);
    cudaGetSymbolAddress((void**)&vT,  g_vT);
    cudaGetSymbolAddress((void**)&vvT, g_vvT);
    cudaGetSymbolAddress((void**)&tmp, g_tmp);
    cudaGetSymbolAddress((void**)&P,   g_P);
    cudaGetSymbolAddress((void**)&rs,  g_rs);
    cudaGetSymbolAddress((void**)&rsp, g_rsp);

    const int SM_PROJ = 49152;   // (16K+8K)*2
    const int SM_QK   = 65536;   // (16K+16K)*2
    const int SM_PV   = 65536;   // (16K+8K+8K)*2

    cudaFuncSetAttribute((const void*)proj_kernel<false, true,  true >, cudaFuncAttributeMaxDynamicSharedMemorySize, SM_PROJ);
    cudaFuncSetAttribute((const void*)proj_kernel<true,  true,  true >, cudaFuncAttributeMaxDynamicSharedMemorySize, SM_PROJ);
    cudaFuncSetAttribute((const void*)proj_kernel<false, false, false>, cudaFuncAttributeMaxDynamicSharedMemorySize, SM_PROJ);
    cudaFuncSetAttribute((const void*)qk_exp_kernel,   cudaFuncAttributeMaxDynamicSharedMemorySize, SM_QK);
    cudaFuncSetAttribute((const void*)fused_pv_kernel, cudaFuncAttributeMaxDynamicSharedMemorySize, SM_PV);

    dim3 blk(256);
    dim3 gProj2(DIM / 64, N_TOK / 128, 2);  // (4, 64, 2)
    dim3 gProj1(DIM / 64, N_TOK / 128, 1);
    dim3 gAttn(N_TOK / 128, N_TOK / 128);   // (64, 64)

    // q (scale 0.125) and k in one launch; vT and vvT (transposed) in another
    proj_kernel<false, true, true><<<gProj2, blk, SM_PROJ>>>(
        x_mean, Wq, bq, q, 0.125f,  x_mean, Wk, bk, k, 1.f, N_TOK);
    proj_kernel<true, true, true><<<gProj2, blk, SM_PROJ>>>(
        x_mean, Wv, bv, vT, 1.f,    x_var, Wvar, bvar, vvT, 1.f, N_TOK);

    qk_exp_kernel<<<gAttn, blk, SM_QK>>>(q, k, P, rsp);
    rs_reduce_kernel<<<N_TOK / 256, 256>>>(rsp, rs);

    fused_pv_kernel<<<gProj1, blk, SM_PV>>>(P, vT, vvT, rs, tmp, out_var);

    proj_kernel<false, false, false><<<gProj1, blk, SM_PROJ>>>(
        tmp, Wo, bo, out_mean, 1.f, tmp, Wo, bo, out_mean, 1.f, N_TOK);
}